// round 1
// baseline (speedup 1.0000x reference)
#include <cuda_runtime.h>
#include <math.h>
#include <stdint.h>

#define Bq 1024
#define Nn 50
#define Hh 128
#define Tt 50
#define Gg 8
#define FULLMASK 0xffffffffu

// Scratch (allocation-free rule: __device__ globals)
__device__ float g_ctx[Bq * Nn * Hh];
__device__ float g_eg [Bq * Nn * Hh];
__device__ float g_ep [Bq * Nn * Hh];

__device__ __forceinline__ float my_tanh(float x) {
    // tanh(x) = 1 - 2/(exp(2x)+1); NaN-free at +-inf, abs err ~5e-7
    float e = __expf(2.0f * x);
    return 1.0f - __fdividef(2.0f, e + 1.0f);
}
__device__ __forceinline__ float my_sig(float x) {
    return __fdividef(1.0f, 1.0f + __expf(-x));
}

// ---------------- Phase A: context, e_g, e_p ----------------
__global__ __launch_bounds__(256) void k_pre(
    const float* __restrict__ pnt, const float* __restrict__ Wemb,
    const float* __restrict__ bemb, const float* __restrict__ Wrg,
    const float* __restrict__ Wrp)
{
    __shared__ __align__(16) float sctx[64][128];
    int row0 = blockIdx.x * 64;
    int tid = threadIdx.x;
    for (int i = tid; i < 64 * 128; i += 256) {
        int r = i >> 7, h = i & 127;
        int row = row0 + r;
        float px = pnt[row * 2 + 0], py = pnt[row * 2 + 1];
        float v = fmaf(px, Wemb[h], fmaf(py, Wemb[128 + h], bemb[h]));
        sctx[r][h] = v;
        g_ctx[(size_t)row * 128 + h] = v;
    }
    __syncthreads();
    int jj = tid & 127, half = tid >> 7;
    int rbase = half * 32;
    // e_g pass
    {
        float acc[32];
        #pragma unroll
        for (int r = 0; r < 32; r++) acc[r] = 0.f;
        for (int k4 = 0; k4 < 32; k4++) {
            float w0 = Wrg[(4 * k4 + 0) * 128 + jj];
            float w1 = Wrg[(4 * k4 + 1) * 128 + jj];
            float w2 = Wrg[(4 * k4 + 2) * 128 + jj];
            float w3 = Wrg[(4 * k4 + 3) * 128 + jj];
            #pragma unroll
            for (int r = 0; r < 32; r++) {
                float4 c = reinterpret_cast<const float4*>(&sctx[rbase + r][0])[k4];
                acc[r] = fmaf(w0, c.x, fmaf(w1, c.y, fmaf(w2, c.z, fmaf(w3, c.w, acc[r]))));
            }
        }
        for (int r = 0; r < 32; r++)
            g_eg[(size_t)(row0 + rbase + r) * 128 + jj] = acc[r];
    }
    // e_p pass
    {
        float acc[32];
        #pragma unroll
        for (int r = 0; r < 32; r++) acc[r] = 0.f;
        for (int k4 = 0; k4 < 32; k4++) {
            float w0 = Wrp[(4 * k4 + 0) * 128 + jj];
            float w1 = Wrp[(4 * k4 + 1) * 128 + jj];
            float w2 = Wrp[(4 * k4 + 2) * 128 + jj];
            float w3 = Wrp[(4 * k4 + 3) * 128 + jj];
            #pragma unroll
            for (int r = 0; r < 32; r++) {
                float4 c = reinterpret_cast<const float4*>(&sctx[rbase + r][0])[k4];
                acc[r] = fmaf(w0, c.x, fmaf(w1, c.y, fmaf(w2, c.z, fmaf(w3, c.w, acc[r]))));
            }
        }
        for (int r = 0; r < 32; r++)
            g_ep[(size_t)(row0 + rbase + r) * 128 + jj] = acc[r];
    }
}

// ---------------- Phase B+C: full T-loop, persistent per-CTA ----------------
__global__ __launch_bounds__(256) void k_main(
    const float* __restrict__ pnt, const float* __restrict__ dini,
    const float* __restrict__ Wi, const float* __restrict__ Wh,
    const float* __restrict__ bl,
    const float* __restrict__ Wqg, const float* __restrict__ vg,
    const float* __restrict__ Wqp, const float* __restrict__ vp,
    const float* __restrict__ Wrc, const float* __restrict__ W1,
    const float* __restrict__ b1, const float* __restrict__ W2,
    const float* __restrict__ b2, float* __restrict__ out)
{
    int b0 = blockIdx.x * Gg;
    int tid = threadIdx.x;
    int lane = tid & 31, wid = tid >> 5;
    int jj = tid & 127, half = tid >> 7;
    int bb0 = half * 4;

    __shared__ float sh_h[Gg][128], sh_c[Gg][128], sh_x[Gg][128];
    __shared__ float sh_q[Gg][128], sh_q2[Gg][128];
    __shared__ __align__(16) float4 sh_g4v[Gg][128];   // gates staging (8x512 f32)
    __shared__ float sh_u[Gg][52];
    __shared__ float sh_mask[Gg][52];
    __shared__ float sh_vg[128], sh_vp[128];
    __shared__ int   sh_act[Gg];
    __shared__ float sh_px[Gg], sh_py[Gg], sh_fx[Gg], sh_fy[Gg], sh_R[Gg];

    // init state
    for (int i = tid; i < Gg * 128; i += 256) {
        int b = i >> 7, h = i & 127;
        sh_h[b][h] = 0.f; sh_c[b][h] = 0.f; sh_x[b][h] = dini[h];
    }
    for (int i = tid; i < Gg * 52; i += 256) sh_mask[i / 52][i % 52] = 0.f;
    if (tid < 128) { sh_vg[tid] = vg[tid]; sh_vp[tid] = vp[tid]; }
    if (tid < Gg) sh_R[tid] = 0.f;
    __syncthreads();

    float* oR  = out;
    float* oV  = out + Bq;
    float* oLP = out + 2 * Bq;
    float* oA  = oLP + (size_t)Bq * Tt * Nn;
    float* oC  = oA  + (size_t)Bq * Tt;
    float* oP  = oC  + (size_t)Bq * Tt * 2;

    const float4* Wi4 = reinterpret_cast<const float4*>(Wi);
    const float4* Wh4 = reinterpret_cast<const float4*>(Wh);

    for (int t = 0; t < Tt; t++) {
        // ---- P1a: gates = x@Wi + h@Wh (vectorized over 4-wide j, 4 batches/thread)
        {
            float4 acc[4];
            #pragma unroll
            for (int b = 0; b < 4; b++) acc[b] = make_float4(0.f, 0.f, 0.f, 0.f);
            #pragma unroll 4
            for (int k = 0; k < 128; k++) {
                float4 wi = Wi4[k * 128 + jj];
                float4 wh = Wh4[k * 128 + jj];
                #pragma unroll
                for (int b = 0; b < 4; b++) {
                    float xv = sh_x[bb0 + b][k];
                    float hv = sh_h[bb0 + b][k];
                    acc[b].x = fmaf(wi.x, xv, fmaf(wh.x, hv, acc[b].x));
                    acc[b].y = fmaf(wi.y, xv, fmaf(wh.y, hv, acc[b].y));
                    acc[b].z = fmaf(wi.z, xv, fmaf(wh.z, hv, acc[b].z));
                    acc[b].w = fmaf(wi.w, xv, fmaf(wh.w, hv, acc[b].w));
                }
            }
            #pragma unroll
            for (int b = 0; b < 4; b++) sh_g4v[bb0 + b][jj] = acc[b];
        }
        __syncthreads();
        // ---- P1b: LSTM nonlinearity
        {
            const float* gp;
            float bi_ = bl[jj], bf_ = bl[128 + jj], bg_ = bl[256 + jj], bo_ = bl[384 + jj];
            #pragma unroll
            for (int b = 0; b < 4; b++) {
                int bb = bb0 + b;
                gp = reinterpret_cast<const float*>(&sh_g4v[bb][0]);
                float gi = gp[jj] + bi_;
                float gf = gp[128 + jj] + bf_;
                float gg = gp[256 + jj] + bg_;
                float go = gp[384 + jj] + bo_;
                float c2 = my_sig(gf) * sh_c[bb][jj] + my_sig(gi) * my_tanh(gg);
                sh_c[bb][jj] = c2;
                sh_h[bb][jj] = my_sig(go) * my_tanh(c2);
            }
        }
        __syncthreads();
        // ---- P2: q = h2 @ Wq_g
        {
            float qa[4] = {0.f, 0.f, 0.f, 0.f};
            #pragma unroll 4
            for (int k = 0; k < 128; k++) {
                float w = Wqg[k * 128 + jj];
                #pragma unroll
                for (int b = 0; b < 4; b++) qa[b] = fmaf(w, sh_h[bb0 + b][k], qa[b]);
            }
            #pragma unroll
            for (int b = 0; b < 4; b++) sh_q[bb0 + b][jj] = qa[b];
        }
        __syncthreads();
        // ---- P3: u[b,n] = sum_h tanh(e_g+q)*v_g - 1e9*mask
        for (int r = wid; r < Gg * Nn; r += 8) {
            int b = r / Nn, n = r - b * Nn;
            const float* eg = g_eg + ((size_t)(b0 + b) * Nn + n) * 128;
            float s = 0.f;
            #pragma unroll
            for (int c4 = 0; c4 < 4; c4++) {
                int h = lane + 32 * c4;
                s = fmaf(my_tanh(eg[h] + sh_q[b][h]), sh_vg[h], s);
            }
            #pragma unroll
            for (int o = 16; o; o >>= 1) s += __shfl_xor_sync(FULLMASK, s, o);
            if (lane == 0) sh_u[b][n] = s - 1e9f * sh_mask[b][n];
        }
        __syncthreads();
        // ---- softmax(u) -> p stored back to sh_u (warp b handles batch b)
        {
            int b = wid;
            float l0 = sh_u[b][lane];
            float l1 = (lane < 18) ? sh_u[b][lane + 32] : -1e38f;
            float m = fmaxf(l0, l1);
            #pragma unroll
            for (int o = 16; o; o >>= 1) m = fmaxf(m, __shfl_xor_sync(FULLMASK, m, o));
            float e0 = __expf(l0 - m);
            float e1 = (lane < 18) ? __expf(l1 - m) : 0.f;
            float s = e0 + e1;
            #pragma unroll
            for (int o = 16; o; o >>= 1) s += __shfl_xor_sync(FULLMASK, s, o);
            float inv = __fdividef(1.f, s);
            sh_u[b][lane] = e0 * inv;
            if (lane < 18) sh_u[b][lane + 32] = e1 * inv;
        }
        __syncthreads();
        // ---- glimpse: g = p @ e_g  -> overwrite sh_q
        {
            float ga[4] = {0.f, 0.f, 0.f, 0.f};
            const float* e0p = g_eg + ((size_t)(b0 + bb0 + 0) * Nn) * 128 + jj;
            const float* e1p = g_eg + ((size_t)(b0 + bb0 + 1) * Nn) * 128 + jj;
            const float* e2p = g_eg + ((size_t)(b0 + bb0 + 2) * Nn) * 128 + jj;
            const float* e3p = g_eg + ((size_t)(b0 + bb0 + 3) * Nn) * 128 + jj;
            #pragma unroll 2
            for (int n = 0; n < Nn; n++) {
                ga[0] = fmaf(sh_u[bb0 + 0][n], e0p[n * 128], ga[0]);
                ga[1] = fmaf(sh_u[bb0 + 1][n], e1p[n * 128], ga[1]);
                ga[2] = fmaf(sh_u[bb0 + 2][n], e2p[n * 128], ga[2]);
                ga[3] = fmaf(sh_u[bb0 + 3][n], e3p[n * 128], ga[3]);
            }
            #pragma unroll
            for (int b = 0; b < 4; b++) sh_q[bb0 + b][jj] = ga[b];
        }
        __syncthreads();
        // ---- P4: q2 = g @ Wq_p
        {
            float qa[4] = {0.f, 0.f, 0.f, 0.f};
            #pragma unroll 4
            for (int k = 0; k < 128; k++) {
                float w = Wqp[k * 128 + jj];
                #pragma unroll
                for (int b = 0; b < 4; b++) qa[b] = fmaf(w, sh_q[bb0 + b][k], qa[b]);
            }
            #pragma unroll
            for (int b = 0; b < 4; b++) sh_q2[bb0 + b][jj] = qa[b];
        }
        __syncthreads();
        // ---- P5: logit = 10*tanh(u2) - 1e9*mask
        for (int r = wid; r < Gg * Nn; r += 8) {
            int b = r / Nn, n = r - b * Nn;
            const float* ep = g_ep + ((size_t)(b0 + b) * Nn + n) * 128;
            float s = 0.f;
            #pragma unroll
            for (int c4 = 0; c4 < 4; c4++) {
                int h = lane + 32 * c4;
                s = fmaf(my_tanh(ep[h] + sh_q2[b][h]), sh_vp[h], s);
            }
            #pragma unroll
            for (int o = 16; o; o >>= 1) s += __shfl_xor_sync(FULLMASK, s, o);
            if (lane == 0) sh_u[b][n] = 10.0f * my_tanh(s) - 1e9f * sh_mask[b][n];
        }
        __syncthreads();
        // ---- final: log_softmax / softmax / argmax / outputs / state update
        {
            int b = wid; int gb = b0 + b;
            float l0 = sh_u[b][lane];
            float l1 = (lane < 18) ? sh_u[b][lane + 32] : -1e38f;
            float m = fmaxf(l0, l1);
            #pragma unroll
            for (int o = 16; o; o >>= 1) m = fmaxf(m, __shfl_xor_sync(FULLMASK, m, o));
            float e0 = __expf(l0 - m);
            float e1 = (lane < 18) ? __expf(l1 - m) : 0.f;
            float s = e0 + e1;
            #pragma unroll
            for (int o = 16; o; o >>= 1) s += __shfl_xor_sync(FULLMASK, s, o);
            float lgs = logf(s);
            float p0 = e0 / s;
            float p1 = e1 / s;
            size_t base = ((size_t)gb * Tt + t) * Nn;
            oLP[base + lane] = (l0 - m) - lgs;
            oP [base + lane] = p0;
            if (lane < 18) {
                oLP[base + lane + 32] = (l1 - m) - lgs;
                oP [base + lane + 32] = p1;
            }
            // argmax on prob, first-index tie-break (JAX semantics)
            float bv = p0; int bi = lane;
            if (lane < 18 && p1 > bv) { bv = p1; bi = lane + 32; }
            #pragma unroll
            for (int o = 16; o; o >>= 1) {
                float ov = __shfl_down_sync(FULLMASK, bv, o);
                int   oi = __shfl_down_sync(FULLMASK, bi, o);
                if (ov > bv || (ov == bv && oi < bi)) { bv = ov; bi = oi; }
            }
            if (lane == 0) {
                int a = bi;
                sh_act[b] = a;
                sh_mask[b][a] = 1.0f;
                oA[(size_t)gb * Tt + t] = (float)a;
                float cx = pnt[((size_t)gb * Nn + a) * 2 + 0];
                float cy = pnt[((size_t)gb * Nn + a) * 2 + 1];
                oC[((size_t)gb * Tt + t) * 2 + 0] = cx;
                oC[((size_t)gb * Tt + t) * 2 + 1] = cy;
                if (t == 0) { sh_fx[b] = cx; sh_fy[b] = cy; }
                else {
                    float dx = cx - sh_px[b], dy = cy - sh_py[b];
                    sh_R[b] += sqrtf(dx * dx + dy * dy + 1e-10f);
                }
                sh_px[b] = cx; sh_py[b] = cy;
            }
        }
        __syncthreads();
        // ---- dec_in = context[b, action]
        for (int i = tid; i < Gg * 128; i += 256) {
            int b = i >> 7, h = i & 127;
            sh_x[b][h] = g_ctx[((size_t)(b0 + b) * Nn + sh_act[b]) * 128 + h];
        }
        __syncthreads();
    } // t loop

    // ---- R closing edge
    if (tid < Gg) {
        int b = tid; int gb = b0 + b;
        float dx = sh_fx[b] - sh_px[b], dy = sh_fy[b] - sh_py[b];
        oR[gb] = sh_R[b] + sqrtf(dx * dx + dy * dy + 1e-10f);
    }
    // ---- critic shortcut: hy = dec_last @ Wref_c (glimpse over length-1 enc => softmax==1)
    {
        float ha[4] = {0.f, 0.f, 0.f, 0.f};
        #pragma unroll 4
        for (int k = 0; k < 128; k++) {
            float w = Wrc[k * 128 + jj];
            #pragma unroll
            for (int b = 0; b < 4; b++) ha[b] = fmaf(w, sh_x[bb0 + b][k], ha[b]);
        }
        #pragma unroll
        for (int b = 0; b < 4; b++) sh_q[bb0 + b][jj] = ha[b];
    }
    __syncthreads();
    {
        float za[4] = {0.f, 0.f, 0.f, 0.f};
        #pragma unroll 4
        for (int k = 0; k < 128; k++) {
            float w = W1[k * 128 + jj];
            #pragma unroll
            for (int b = 0; b < 4; b++) za[b] = fmaf(w, sh_q[bb0 + b][k], za[b]);
        }
        float bb1 = b1[jj];
        #pragma unroll
        for (int b = 0; b < 4; b++) sh_q2[bb0 + b][jj] = fmaxf(za[b] + bb1, 0.f);
    }
    __syncthreads();
    {
        int b = wid; int gb = b0 + b;
        float s = 0.f;
        #pragma unroll
        for (int c4 = 0; c4 < 4; c4++) {
            int h = lane + 32 * c4;
            s = fmaf(sh_q2[b][h], W2[h], s);
        }
        #pragma unroll
        for (int o = 16; o; o >>= 1) s += __shfl_xor_sync(FULLMASK, s, o);
        if (lane == 0) oV[gb] = s + b2[0];
    }
}

extern "C" void kernel_launch(void* const* d_in, const int* in_sizes, int n_in,
                              void* d_out, int out_size) {
    const float* pnt  = (const float*)d_in[0];
    const float* Wemb = (const float*)d_in[1];
    const float* bemb = (const float*)d_in[2];
    const float* dini = (const float*)d_in[3];
    const float* Wi   = (const float*)d_in[4];
    const float* Wh   = (const float*)d_in[5];
    const float* bl   = (const float*)d_in[6];
    const float* Wqg  = (const float*)d_in[7];
    const float* Wrg  = (const float*)d_in[8];
    const float* vg   = (const float*)d_in[9];
    const float* Wqp  = (const float*)d_in[10];
    const float* Wrp  = (const float*)d_in[11];
    const float* vp   = (const float*)d_in[12];
    // d_in[13..16]: Wi_c, Wh_c, b_c, Wq_c — provably dead (softmax over length-1 enc)
    const float* Wrc  = (const float*)d_in[17];
    // d_in[18]: v_c — dead
    const float* W1   = (const float*)d_in[19];
    const float* b1   = (const float*)d_in[20];
    const float* W2   = (const float*)d_in[21];
    const float* b2   = (const float*)d_in[22];

    k_pre<<<(Bq * Nn) / 64, 256>>>(pnt, Wemb, bemb, Wrg, Wrp);
    k_main<<<Bq / Gg, 256>>>(pnt, dini, Wi, Wh, bl, Wqg, vg, Wqp, vp,
                             Wrc, W1, b1, W2, b2, (float*)d_out);
}

// round 2
// speedup vs baseline: 1.3541x; 1.3541x over previous
#include <cuda_runtime.h>
#include <math.h>
#include <stdint.h>

#define Bq 1024
#define Nn 50
#define Hh 128
#define Tt 50
#define Gg 8
#define FULLMASK 0xffffffffu

// Scratch (allocation-free rule: __device__ globals)
__device__ float g_ctx[Bq * Nn * Hh];
__device__ float g_eg [Bq * Nn * Hh];
__device__ float g_ep [Bq * Nn * Hh];
__device__ float g_xw [(size_t)Bq * Nn * 512];  // context @ Wi, 100MB
__device__ float g_xw0[512];                    // dec_init @ Wi

__device__ __forceinline__ float my_tanh(float x) {
    float e = __expf(2.0f * x);
    return 1.0f - __fdividef(2.0f, e + 1.0f);
}
__device__ __forceinline__ float my_sig(float x) {
    return __fdividef(1.0f, 1.0f + __expf(-x));
}

// ---------------- Phase A: context, e_g, e_p, ctx@Wi ----------------
__global__ __launch_bounds__(512) void k_pre(
    const float* __restrict__ pnt, const float* __restrict__ Wemb,
    const float* __restrict__ bemb, const float* __restrict__ Wrg,
    const float* __restrict__ Wrp, const float* __restrict__ Wi,
    const float* __restrict__ dini)
{
    if (blockIdx.x == (Bq * Nn) / 64) {
        // dec_init @ Wi : 512 cols, one col per thread
        int j = threadIdx.x;
        float s = 0.f;
        #pragma unroll 4
        for (int k = 0; k < 128; k++) s = fmaf(dini[k], Wi[k * 512 + j], s);
        g_xw0[j] = s;
        return;
    }
    __shared__ __align__(16) float sctx[64][128];
    int row0 = blockIdx.x * 64;
    int tid = threadIdx.x;
    for (int i = tid; i < 64 * 128; i += 512) {
        int r = i >> 7, h = i & 127;
        int row = row0 + r;
        float px = pnt[row * 2 + 0], py = pnt[row * 2 + 1];
        float v = fmaf(px, Wemb[h], fmaf(py, Wemb[128 + h], bemb[h]));
        sctx[r][h] = v;
        g_ctx[(size_t)row * 128 + h] = v;
    }
    __syncthreads();
    int jj = tid & 127;
    int quarter = tid >> 7;           // 0..3
    int rbase = quarter * 16;

#define PRE_PASS(Wptr, LD, COLOFF, OUTptr, LDO)                                   \
    {                                                                             \
        float acc[16];                                                            \
        _Pragma("unroll")                                                         \
        for (int r = 0; r < 16; r++) acc[r] = 0.f;                                \
        for (int k4 = 0; k4 < 32; k4++) {                                         \
            float w0 = Wptr[(4 * k4 + 0) * LD + COLOFF + jj];                     \
            float w1 = Wptr[(4 * k4 + 1) * LD + COLOFF + jj];                     \
            float w2 = Wptr[(4 * k4 + 2) * LD + COLOFF + jj];                     \
            float w3 = Wptr[(4 * k4 + 3) * LD + COLOFF + jj];                     \
            _Pragma("unroll")                                                     \
            for (int r = 0; r < 16; r++) {                                        \
                float4 c = reinterpret_cast<const float4*>(&sctx[rbase + r][0])[k4]; \
                acc[r] = fmaf(w0, c.x, fmaf(w1, c.y, fmaf(w2, c.z, fmaf(w3, c.w, acc[r])))); \
            }                                                                     \
        }                                                                         \
        _Pragma("unroll")                                                         \
        for (int r = 0; r < 16; r++)                                              \
            OUTptr[(size_t)(row0 + rbase + r) * LDO + COLOFF + jj] = acc[r];      \
    }

    PRE_PASS(Wrg, 128, 0, g_eg, 128);
    PRE_PASS(Wrp, 128, 0, g_ep, 128);
    PRE_PASS(Wi, 512, 0,   g_xw, 512);
    PRE_PASS(Wi, 512, 128, g_xw, 512);
    PRE_PASS(Wi, 512, 256, g_xw, 512);
    PRE_PASS(Wi, 512, 384, g_xw, 512);
#undef PRE_PASS
}

// ---------------- Phase B+C: full T-loop, persistent per-CTA ----------------
__global__ __launch_bounds__(512) void k_main(
    const float* __restrict__ pnt, const float* __restrict__ Wh,
    const float* __restrict__ bl,
    const float* __restrict__ Wqg, const float* __restrict__ vg,
    const float* __restrict__ Wqp, const float* __restrict__ vp,
    const float* __restrict__ Wrc, const float* __restrict__ W1,
    const float* __restrict__ b1, const float* __restrict__ W2,
    const float* __restrict__ b2, float* __restrict__ out)
{
    int b0 = blockIdx.x * Gg;
    int tid = threadIdx.x;
    int lane = tid & 31, wid = tid >> 5;   // 16 warps
    int jj = tid & 127;
    int q4 = tid >> 7;                     // 0..3
    int khalf = q4 & 1;                    // k-range split for gates
    int bhalf = q4 >> 1;                   // batch-group split for gates
    int bb0g = bhalf * 4;                  // gates: 4 batches each
    int bb0q = q4 * 2;                     // small GEMMs: 2 batches each

    __shared__ float sh_h[Gg][128], sh_c[Gg][128], sh_x[Gg][128];
    __shared__ float sh_q[Gg][128], sh_q2[Gg][128];
    __shared__ __align__(16) float4 sh_gates[Gg][128];  // 16KB: xw + x@... staged gates
    __shared__ float sh_u[Gg][52];
    __shared__ float sh_mask[Gg][52];
    __shared__ float sh_vg[128], sh_vp[128];
    __shared__ int   sh_act[Gg];
    __shared__ float sh_px[Gg], sh_py[Gg], sh_fx[Gg], sh_fy[Gg], sh_R[Gg];

    for (int i = tid; i < Gg * 128; i += 512) {
        int b = i >> 7, h = i & 127;
        sh_h[b][h] = 0.f; sh_c[b][h] = 0.f;
    }
    for (int i = tid; i < Gg * 52; i += 512) sh_mask[i / 52][i % 52] = 0.f;
    if (tid < 128) { sh_vg[tid] = vg[tid]; sh_vp[tid] = vp[tid]; }
    if (tid < Gg) sh_R[tid] = 0.f;
    __syncthreads();

    float* oR  = out;
    float* oV  = out + Bq;
    float* oLP = out + 2 * Bq;
    float* oA  = oLP + (size_t)Bq * Tt * Nn;
    float* oC  = oA  + (size_t)Bq * Tt;
    float* oP  = oC  + (size_t)Bq * Tt * 2;

    const float4* Wh4 = reinterpret_cast<const float4*>(Wh);

    for (int t = 0; t < Tt; t++) {
        // ---- gather precomputed x@Wi rows into gates staging
        #pragma unroll
        for (int i = tid; i < Gg * 128; i += 512) {
            int b = i >> 7, j = i & 127;
            const float4* row = (t == 0)
                ? reinterpret_cast<const float4*>(g_xw0)
                : reinterpret_cast<const float4*>(g_xw + ((size_t)(b0 + b) * Nn + sh_act[b]) * 512);
            sh_gates[b][j] = row[j];
        }
        __syncthreads();
        // ---- gates += h@Wh  (k-split across khalf, 4 batches per thread)
        {
            float4 acc[4];
            #pragma unroll
            for (int b = 0; b < 4; b++) acc[b] = make_float4(0.f, 0.f, 0.f, 0.f);
            int k0 = khalf * 64;
            #pragma unroll 4
            for (int k = k0; k < k0 + 64; k++) {
                float4 wh = Wh4[k * 128 + jj];
                #pragma unroll
                for (int b = 0; b < 4; b++) {
                    float hv = sh_h[bb0g + b][k];
                    acc[b].x = fmaf(wh.x, hv, acc[b].x);
                    acc[b].y = fmaf(wh.y, hv, acc[b].y);
                    acc[b].z = fmaf(wh.z, hv, acc[b].z);
                    acc[b].w = fmaf(wh.w, hv, acc[b].w);
                }
            }
            if (khalf == 1) {
                #pragma unroll
                for (int b = 0; b < 4; b++) {
                    float4 p = sh_gates[bb0g + b][jj];
                    p.x += acc[b].x; p.y += acc[b].y; p.z += acc[b].z; p.w += acc[b].w;
                    sh_gates[bb0g + b][jj] = p;
                }
            }
            __syncthreads();
            if (khalf == 0) {
                #pragma unroll
                for (int b = 0; b < 4; b++) {
                    float4 p = sh_gates[bb0g + b][jj];
                    p.x += acc[b].x; p.y += acc[b].y; p.z += acc[b].z; p.w += acc[b].w;
                    sh_gates[bb0g + b][jj] = p;
                }
            }
        }
        __syncthreads();
        // ---- LSTM pointwise (1024 elems, 2 per thread)
        #pragma unroll
        for (int i = tid; i < Gg * 128; i += 512) {
            int b = i >> 7, j = i & 127;
            const float* gp = reinterpret_cast<const float*>(&sh_gates[b][0]);
            float gi = gp[j]       + bl[j];
            float gf = gp[128 + j] + bl[128 + j];
            float gg = gp[256 + j] + bl[256 + j];
            float go = gp[384 + j] + bl[384 + j];
            float c2 = my_sig(gf) * sh_c[b][j] + my_sig(gi) * my_tanh(gg);
            sh_c[b][j] = c2;
            sh_h[b][j] = my_sig(go) * my_tanh(c2);
        }
        __syncthreads();
        // ---- q = h2 @ Wq_g (2 batches per thread-group)
        {
            float qa0 = 0.f, qa1 = 0.f;
            #pragma unroll 4
            for (int k = 0; k < 128; k++) {
                float w = Wqg[k * 128 + jj];
                qa0 = fmaf(w, sh_h[bb0q + 0][k], qa0);
                qa1 = fmaf(w, sh_h[bb0q + 1][k], qa1);
            }
            sh_q[bb0q + 0][jj] = qa0;
            sh_q[bb0q + 1][jj] = qa1;
        }
        __syncthreads();
        // ---- u[b,n] = sum_h tanh(e_g+q)*v_g - 1e9*mask  (16 warps, 400 rows)
        for (int r = wid; r < Gg * Nn; r += 16) {
            int b = r / Nn, n = r - b * Nn;
            const float* eg = g_eg + ((size_t)(b0 + b) * Nn + n) * 128;
            float s = 0.f;
            #pragma unroll
            for (int c4 = 0; c4 < 4; c4++) {
                int h = lane + 32 * c4;
                s = fmaf(my_tanh(eg[h] + sh_q[b][h]), sh_vg[h], s);
            }
            #pragma unroll
            for (int o = 16; o; o >>= 1) s += __shfl_xor_sync(FULLMASK, s, o);
            if (lane == 0) sh_u[b][n] = s - 1e9f * sh_mask[b][n];
        }
        __syncthreads();
        // ---- softmax(u) -> p (warp b handles batch b)
        if (wid < Gg) {
            int b = wid;
            float l0 = sh_u[b][lane];
            float l1 = (lane < 18) ? sh_u[b][lane + 32] : -1e38f;
            float m = fmaxf(l0, l1);
            #pragma unroll
            for (int o = 16; o; o >>= 1) m = fmaxf(m, __shfl_xor_sync(FULLMASK, m, o));
            float e0 = __expf(l0 - m);
            float e1 = (lane < 18) ? __expf(l1 - m) : 0.f;
            float s = e0 + e1;
            #pragma unroll
            for (int o = 16; o; o >>= 1) s += __shfl_xor_sync(FULLMASK, s, o);
            float inv = __fdividef(1.f, s);
            sh_u[b][lane] = e0 * inv;
            if (lane < 18) sh_u[b][lane + 32] = e1 * inv;
        }
        __syncthreads();
        // ---- glimpse: g = p @ e_g -> sh_q (2 batches per group)
        {
            float ga0 = 0.f, ga1 = 0.f;
            const float* e0p = g_eg + ((size_t)(b0 + bb0q + 0) * Nn) * 128 + jj;
            const float* e1p = g_eg + ((size_t)(b0 + bb0q + 1) * Nn) * 128 + jj;
            #pragma unroll 2
            for (int n = 0; n < Nn; n++) {
                ga0 = fmaf(sh_u[bb0q + 0][n], e0p[n * 128], ga0);
                ga1 = fmaf(sh_u[bb0q + 1][n], e1p[n * 128], ga1);
            }
            sh_q[bb0q + 0][jj] = ga0;
            sh_q[bb0q + 1][jj] = ga1;
        }
        __syncthreads();
        // ---- q2 = g @ Wq_p
        {
            float qa0 = 0.f, qa1 = 0.f;
            #pragma unroll 4
            for (int k = 0; k < 128; k++) {
                float w = Wqp[k * 128 + jj];
                qa0 = fmaf(w, sh_q[bb0q + 0][k], qa0);
                qa1 = fmaf(w, sh_q[bb0q + 1][k], qa1);
            }
            sh_q2[bb0q + 0][jj] = qa0;
            sh_q2[bb0q + 1][jj] = qa1;
        }
        __syncthreads();
        // ---- logit = 10*tanh(u2) - 1e9*mask
        for (int r = wid; r < Gg * Nn; r += 16) {
            int b = r / Nn, n = r - b * Nn;
            const float* ep = g_ep + ((size_t)(b0 + b) * Nn + n) * 128;
            float s = 0.f;
            #pragma unroll
            for (int c4 = 0; c4 < 4; c4++) {
                int h = lane + 32 * c4;
                s = fmaf(my_tanh(ep[h] + sh_q2[b][h]), sh_vp[h], s);
            }
            #pragma unroll
            for (int o = 16; o; o >>= 1) s += __shfl_xor_sync(FULLMASK, s, o);
            if (lane == 0) sh_u[b][n] = 10.0f * my_tanh(s) - 1e9f * sh_mask[b][n];
        }
        __syncthreads();
        // ---- final: log_softmax / softmax / argmax / outputs / state
        if (wid < Gg) {
            int b = wid; int gb = b0 + b;
            float l0 = sh_u[b][lane];
            float l1 = (lane < 18) ? sh_u[b][lane + 32] : -1e38f;
            float m = fmaxf(l0, l1);
            #pragma unroll
            for (int o = 16; o; o >>= 1) m = fmaxf(m, __shfl_xor_sync(FULLMASK, m, o));
            float e0 = __expf(l0 - m);
            float e1 = (lane < 18) ? __expf(l1 - m) : 0.f;
            float s = e0 + e1;
            #pragma unroll
            for (int o = 16; o; o >>= 1) s += __shfl_xor_sync(FULLMASK, s, o);
            float lgs = logf(s);
            float p0 = e0 / s;
            float p1 = e1 / s;
            size_t base = ((size_t)gb * Tt + t) * Nn;
            oLP[base + lane] = (l0 - m) - lgs;
            oP [base + lane] = p0;
            if (lane < 18) {
                oLP[base + lane + 32] = (l1 - m) - lgs;
                oP [base + lane + 32] = p1;
            }
            float bv = p0; int bi = lane;
            if (lane < 18 && p1 > bv) { bv = p1; bi = lane + 32; }
            #pragma unroll
            for (int o = 16; o; o >>= 1) {
                float ov = __shfl_down_sync(FULLMASK, bv, o);
                int   oi = __shfl_down_sync(FULLMASK, bi, o);
                if (ov > bv || (ov == bv && oi < bi)) { bv = ov; bi = oi; }
            }
            if (lane == 0) {
                int a = bi;
                sh_act[b] = a;
                sh_mask[b][a] = 1.0f;
                oA[(size_t)gb * Tt + t] = (float)a;
                float cx = pnt[((size_t)gb * Nn + a) * 2 + 0];
                float cy = pnt[((size_t)gb * Nn + a) * 2 + 1];
                oC[((size_t)gb * Tt + t) * 2 + 0] = cx;
                oC[((size_t)gb * Tt + t) * 2 + 1] = cy;
                if (t == 0) { sh_fx[b] = cx; sh_fy[b] = cy; }
                else {
                    float dx = cx - sh_px[b], dy = cy - sh_py[b];
                    sh_R[b] += sqrtf(dx * dx + dy * dy + 1e-10f);
                }
                sh_px[b] = cx; sh_py[b] = cy;
            }
        }
        __syncthreads();
    } // t loop

    // ---- R closing edge
    if (tid < Gg) {
        int b = tid; int gb = b0 + b;
        float dx = sh_fx[b] - sh_px[b], dy = sh_fy[b] - sh_py[b];
        oR[gb] = sh_R[b] + sqrtf(dx * dx + dy * dy + 1e-10f);
    }
    // ---- dec_last = context[b, last action]
    #pragma unroll
    for (int i = tid; i < Gg * 128; i += 512) {
        int b = i >> 7, h = i & 127;
        sh_x[b][h] = g_ctx[((size_t)(b0 + b) * Nn + sh_act[b]) * 128 + h];
    }
    __syncthreads();
    // ---- critic shortcut: hy = dec_last @ Wref_c (softmax over length-1 enc == 1)
    {
        float ha0 = 0.f, ha1 = 0.f;
        #pragma unroll 4
        for (int k = 0; k < 128; k++) {
            float w = Wrc[k * 128 + jj];
            ha0 = fmaf(w, sh_x[bb0q + 0][k], ha0);
            ha1 = fmaf(w, sh_x[bb0q + 1][k], ha1);
        }
        sh_q[bb0q + 0][jj] = ha0;
        sh_q[bb0q + 1][jj] = ha1;
    }
    __syncthreads();
    {
        float za0 = 0.f, za1 = 0.f;
        #pragma unroll 4
        for (int k = 0; k < 128; k++) {
            float w = W1[k * 128 + jj];
            za0 = fmaf(w, sh_q[bb0q + 0][k], za0);
            za1 = fmaf(w, sh_q[bb0q + 1][k], za1);
        }
        float bb1 = b1[jj];
        sh_q2[bb0q + 0][jj] = fmaxf(za0 + bb1, 0.f);
        sh_q2[bb0q + 1][jj] = fmaxf(za1 + bb1, 0.f);
    }
    __syncthreads();
    if (wid < Gg) {
        int b = wid; int gb = b0 + b;
        float s = 0.f;
        #pragma unroll
        for (int c4 = 0; c4 < 4; c4++) {
            int h = lane + 32 * c4;
            s = fmaf(sh_q2[b][h], W2[h], s);
        }
        #pragma unroll
        for (int o = 16; o; o >>= 1) s += __shfl_xor_sync(FULLMASK, s, o);
        if (lane == 0) oV[gb] = s + b2[0];
    }
}

extern "C" void kernel_launch(void* const* d_in, const int* in_sizes, int n_in,
                              void* d_out, int out_size) {
    const float* pnt  = (const float*)d_in[0];
    const float* Wemb = (const float*)d_in[1];
    const float* bemb = (const float*)d_in[2];
    const float* dini = (const float*)d_in[3];
    const float* Wi   = (const float*)d_in[4];
    const float* Wh   = (const float*)d_in[5];
    const float* bl   = (const float*)d_in[6];
    const float* Wqg  = (const float*)d_in[7];
    const float* Wrg  = (const float*)d_in[8];
    const float* vg   = (const float*)d_in[9];
    const float* Wqp  = (const float*)d_in[10];
    const float* Wrp  = (const float*)d_in[11];
    const float* vp   = (const float*)d_in[12];
    // d_in[13..16]: Wi_c, Wh_c, b_c, Wq_c — dead (softmax over length-1 enc)
    const float* Wrc  = (const float*)d_in[17];
    // d_in[18]: v_c — dead
    const float* W1   = (const float*)d_in[19];
    const float* b1   = (const float*)d_in[20];
    const float* W2   = (const float*)d_in[21];
    const float* b2   = (const float*)d_in[22];

    k_pre<<<(Bq * Nn) / 64 + 1, 512>>>(pnt, Wemb, bemb, Wrg, Wrp, Wi, dini);
    k_main<<<Bq / Gg, 512>>>(pnt, Wh, bl, Wqg, vg, Wqp, vp,
                             Wrc, W1, b1, W2, b2, (float*)d_out);
}

// round 3
// speedup vs baseline: 1.7601x; 1.2998x over previous
#include <cuda_runtime.h>
#include <math.h>
#include <stdint.h>

#define Bq 1024
#define Nn 50
#define Hh 128
#define Tt 50
#define Gg 4
#define FULLMASK 0xffffffffu

// Scratch (allocation-free rule: __device__ globals)
__device__ float g_ctx[Bq * Nn * Hh];
__device__ float g_eg [Bq * Nn * Hh];
__device__ float g_ep [Bq * Nn * Hh];
__device__ float g_xw [(size_t)Bq * Nn * 512];  // context @ Wi
__device__ float g_xw0[512];                    // dec_init @ Wi

__device__ __forceinline__ float my_tanh(float x) {
    float e = __expf(2.0f * x);
    return 1.0f - __fdividef(2.0f, e + 1.0f);
}
__device__ __forceinline__ float my_sig(float x) {
    return __fdividef(1.0f, 1.0f + __expf(-x));
}

// ---------------- Phase A: context, e_g, e_p, ctx@Wi ----------------
__global__ __launch_bounds__(512) void k_pre(
    const float* __restrict__ pnt, const float* __restrict__ Wemb,
    const float* __restrict__ bemb, const float* __restrict__ Wrg,
    const float* __restrict__ Wrp, const float* __restrict__ Wi,
    const float* __restrict__ dini)
{
    if (blockIdx.x == (Bq * Nn) / 64) {
        int j = threadIdx.x;
        float s = 0.f;
        #pragma unroll 4
        for (int k = 0; k < 128; k++) s = fmaf(dini[k], Wi[k * 512 + j], s);
        g_xw0[j] = s;
        return;
    }
    __shared__ __align__(16) float sctx[64][128];
    int row0 = blockIdx.x * 64;
    int tid = threadIdx.x;
    for (int i = tid; i < 64 * 128; i += 512) {
        int r = i >> 7, h = i & 127;
        int row = row0 + r;
        float px = pnt[row * 2 + 0], py = pnt[row * 2 + 1];
        float v = fmaf(px, Wemb[h], fmaf(py, Wemb[128 + h], bemb[h]));
        sctx[r][h] = v;
        g_ctx[(size_t)row * 128 + h] = v;
    }
    __syncthreads();
    int jj = tid & 127;
    int quarter = tid >> 7;
    int rbase = quarter * 16;

#define PRE_PASS(Wptr, LD, COLOFF, OUTptr, LDO)                                   \
    {                                                                             \
        float acc[16];                                                            \
        _Pragma("unroll")                                                         \
        for (int r = 0; r < 16; r++) acc[r] = 0.f;                                \
        for (int k4 = 0; k4 < 32; k4++) {                                         \
            float w0 = Wptr[(4 * k4 + 0) * LD + COLOFF + jj];                     \
            float w1 = Wptr[(4 * k4 + 1) * LD + COLOFF + jj];                     \
            float w2 = Wptr[(4 * k4 + 2) * LD + COLOFF + jj];                     \
            float w3 = Wptr[(4 * k4 + 3) * LD + COLOFF + jj];                     \
            _Pragma("unroll")                                                     \
            for (int r = 0; r < 16; r++) {                                        \
                float4 c = reinterpret_cast<const float4*>(&sctx[rbase + r][0])[k4]; \
                acc[r] = fmaf(w0, c.x, fmaf(w1, c.y, fmaf(w2, c.z, fmaf(w3, c.w, acc[r])))); \
            }                                                                     \
        }                                                                         \
        _Pragma("unroll")                                                         \
        for (int r = 0; r < 16; r++)                                              \
            OUTptr[(size_t)(row0 + rbase + r) * LDO + COLOFF + jj] = acc[r];      \
    }

    PRE_PASS(Wrg, 128, 0, g_eg, 128);
    PRE_PASS(Wrp, 128, 0, g_ep, 128);
    PRE_PASS(Wi, 512, 0,   g_xw, 512);
    PRE_PASS(Wi, 512, 128, g_xw, 512);
    PRE_PASS(Wi, 512, 256, g_xw, 512);
    PRE_PASS(Wi, 512, 384, g_xw, 512);
#undef PRE_PASS
}

// ---------------- Phase B+C: full T-loop, 2 CTAs/SM ----------------
__global__ __launch_bounds__(512, 2) void k_main(
    const float* __restrict__ pnt, const float* __restrict__ Wh,
    const float* __restrict__ bl,
    const float* __restrict__ Wqg, const float* __restrict__ vg,
    const float* __restrict__ Wqp, const float* __restrict__ vp,
    const float* __restrict__ Wrc, const float* __restrict__ W1,
    const float* __restrict__ b1, const float* __restrict__ W2,
    const float* __restrict__ b2, float* __restrict__ out)
{
    int b0 = blockIdx.x * Gg;
    int tid = threadIdx.x;
    int lane = tid & 31, wid = tid >> 5;   // 16 warps
    int jj = tid & 127;
    int q4 = tid >> 7;                     // 0..3 : k-quarter (gates) / batch id (others)

    // sh_part[q][b][jj] : gates partials; sh_part[0] doubles as the final gates buffer
    __shared__ __align__(16) float4 sh_part[4][Gg][128];       // 32 KB
    __shared__ float sh_h[Gg][128], sh_c[Gg][128];             // 4 KB
    __shared__ float sh_q[Gg][128], sh_q2[Gg][128];            // 4 KB
    __shared__ float sh_u[Gg][52], sh_mask[Gg][52];            // 1.7 KB
    __shared__ float sh_vg[128], sh_vp[128];
    __shared__ int   sh_act[Gg];
    __shared__ float sh_px[Gg], sh_py[Gg], sh_fx[Gg], sh_fy[Gg], sh_R[Gg];

    for (int i = tid; i < Gg * 128; i += 512) {
        int b = i >> 7, h = i & 127;
        sh_h[b][h] = 0.f; sh_c[b][h] = 0.f;
    }
    for (int i = tid; i < Gg * 52; i += 512) sh_mask[i / 52][i % 52] = 0.f;
    if (tid < 128) { sh_vg[tid] = vg[tid]; sh_vp[tid] = vp[tid]; }
    if (tid < Gg) sh_R[tid] = 0.f;
    __syncthreads();

    float* oR  = out;
    float* oV  = out + Bq;
    float* oLP = out + 2 * Bq;
    float* oA  = oLP + (size_t)Bq * Tt * Nn;
    float* oC  = oA  + (size_t)Bq * Tt;
    float* oP  = oC  + (size_t)Bq * Tt * 2;

    const float4* Wh4 = reinterpret_cast<const float4*>(Wh);

    for (int t = 0; t < Tt; t++) {
        // ---- P0: gates partials, 4-way k-split (Wh read exactly once per CTA)
        {
            float4 acc[Gg];
            #pragma unroll
            for (int b = 0; b < Gg; b++) acc[b] = make_float4(0.f, 0.f, 0.f, 0.f);
            int k0 = q4 * 32;
            #pragma unroll 4
            for (int k = k0; k < k0 + 32; k++) {
                float4 wh = Wh4[k * 128 + jj];
                #pragma unroll
                for (int b = 0; b < Gg; b++) {
                    float hv = sh_h[b][k];
                    acc[b].x = fmaf(wh.x, hv, acc[b].x);
                    acc[b].y = fmaf(wh.y, hv, acc[b].y);
                    acc[b].z = fmaf(wh.z, hv, acc[b].z);
                    acc[b].w = fmaf(wh.w, hv, acc[b].w);
                }
            }
            #pragma unroll
            for (int b = 0; b < Gg; b++) sh_part[q4][b][jj] = acc[b];
        }
        __syncthreads();
        // ---- P1: reduce partials + x@Wi gather -> sh_part[0] (final gates)
        {
            int b = q4;
            const float4* row = (t == 0)
                ? reinterpret_cast<const float4*>(g_xw0)
                : reinterpret_cast<const float4*>(g_xw + ((size_t)(b0 + b) * Nn + sh_act[b]) * 512);
            float4 s = row[jj];
            #pragma unroll
            for (int q = 0; q < 4; q++) {
                float4 p = sh_part[q][b][jj];
                s.x += p.x; s.y += p.y; s.z += p.z; s.w += p.w;
            }
            sh_part[0][b][jj] = s;
        }
        __syncthreads();
        // ---- P2: LSTM pointwise (thread = (b=q4, j=jj))
        {
            int b = q4, j = jj;
            const float* gp = reinterpret_cast<const float*>(&sh_part[0][b][0]);
            float gi = gp[j]       + bl[j];
            float gf = gp[128 + j] + bl[128 + j];
            float gg = gp[256 + j] + bl[256 + j];
            float go = gp[384 + j] + bl[384 + j];
            float c2 = my_sig(gf) * sh_c[b][j] + my_sig(gi) * my_tanh(gg);
            sh_c[b][j] = c2;
            sh_h[b][j] = my_sig(go) * my_tanh(c2);
        }
        __syncthreads();
        // ---- P3: q = h2 @ Wq_g (thread = (b, jj), full K; Wqg L1-resident)
        {
            int b = q4;
            float qa = 0.f;
            #pragma unroll 4
            for (int k = 0; k < 128; k++)
                qa = fmaf(Wqg[k * 128 + jj], sh_h[b][k], qa);
            sh_q[b][jj] = qa;
        }
        __syncthreads();
        // ---- P4: u[b,n] = sum_h tanh(e_g+q)*v_g - 1e9*mask (200 rows / 16 warps)
        for (int r = wid; r < Gg * Nn; r += 16) {
            int b = r / Nn, n = r - b * Nn;
            const float* eg = g_eg + ((size_t)(b0 + b) * Nn + n) * 128;
            float s = 0.f;
            #pragma unroll
            for (int c4 = 0; c4 < 4; c4++) {
                int h = lane + 32 * c4;
                s = fmaf(my_tanh(eg[h] + sh_q[b][h]), sh_vg[h], s);
            }
            #pragma unroll
            for (int o = 16; o; o >>= 1) s += __shfl_xor_sync(FULLMASK, s, o);
            if (lane == 0) sh_u[b][n] = s - 1e9f * sh_mask[b][n];
        }
        __syncthreads();
        // ---- P5: softmax(u) -> p (warp b handles batch b)
        if (wid < Gg) {
            int b = wid;
            float l0 = sh_u[b][lane];
            float l1 = (lane < 18) ? sh_u[b][lane + 32] : -1e38f;
            float m = fmaxf(l0, l1);
            #pragma unroll
            for (int o = 16; o; o >>= 1) m = fmaxf(m, __shfl_xor_sync(FULLMASK, m, o));
            float e0 = __expf(l0 - m);
            float e1 = (lane < 18) ? __expf(l1 - m) : 0.f;
            float s = e0 + e1;
            #pragma unroll
            for (int o = 16; o; o >>= 1) s += __shfl_xor_sync(FULLMASK, s, o);
            float inv = __fdividef(1.f, s);
            sh_u[b][lane] = e0 * inv;
            if (lane < 18) sh_u[b][lane + 32] = e1 * inv;
        }
        __syncthreads();
        // ---- P6: glimpse g = p @ e_g -> sh_q
        {
            int b = q4;
            const float* ep = g_eg + ((size_t)(b0 + b) * Nn) * 128 + jj;
            float ga = 0.f;
            #pragma unroll 2
            for (int n = 0; n < Nn; n++)
                ga = fmaf(sh_u[b][n], ep[n * 128], ga);
            sh_q[b][jj] = ga;
        }
        __syncthreads();
        // ---- P7: q2 = g @ Wq_p
        {
            int b = q4;
            float qa = 0.f;
            #pragma unroll 4
            for (int k = 0; k < 128; k++)
                qa = fmaf(Wqp[k * 128 + jj], sh_q[b][k], qa);
            sh_q2[b][jj] = qa;
        }
        __syncthreads();
        // ---- P8: logit = 10*tanh(u2) - 1e9*mask
        for (int r = wid; r < Gg * Nn; r += 16) {
            int b = r / Nn, n = r - b * Nn;
            const float* ep = g_ep + ((size_t)(b0 + b) * Nn + n) * 128;
            float s = 0.f;
            #pragma unroll
            for (int c4 = 0; c4 < 4; c4++) {
                int h = lane + 32 * c4;
                s = fmaf(my_tanh(ep[h] + sh_q2[b][h]), sh_vp[h], s);
            }
            #pragma unroll
            for (int o = 16; o; o >>= 1) s += __shfl_xor_sync(FULLMASK, s, o);
            if (lane == 0) sh_u[b][n] = 10.0f * my_tanh(s) - 1e9f * sh_mask[b][n];
        }
        __syncthreads();
        // ---- P9: log_softmax / softmax / argmax / outputs / state
        if (wid < Gg) {
            int b = wid; int gb = b0 + b;
            float l0 = sh_u[b][lane];
            float l1 = (lane < 18) ? sh_u[b][lane + 32] : -1e38f;
            float m = fmaxf(l0, l1);
            #pragma unroll
            for (int o = 16; o; o >>= 1) m = fmaxf(m, __shfl_xor_sync(FULLMASK, m, o));
            float e0 = __expf(l0 - m);
            float e1 = (lane < 18) ? __expf(l1 - m) : 0.f;
            float s = e0 + e1;
            #pragma unroll
            for (int o = 16; o; o >>= 1) s += __shfl_xor_sync(FULLMASK, s, o);
            float lgs = logf(s);
            float p0 = e0 / s;
            float p1 = e1 / s;
            size_t base = ((size_t)gb * Tt + t) * Nn;
            oLP[base + lane] = (l0 - m) - lgs;
            oP [base + lane] = p0;
            if (lane < 18) {
                oLP[base + lane + 32] = (l1 - m) - lgs;
                oP [base + lane + 32] = p1;
            }
            float bv = p0; int bi = lane;
            if (lane < 18 && p1 > bv) { bv = p1; bi = lane + 32; }
            #pragma unroll
            for (int o = 16; o; o >>= 1) {
                float ov = __shfl_down_sync(FULLMASK, bv, o);
                int   oi = __shfl_down_sync(FULLMASK, bi, o);
                if (ov > bv || (ov == bv && oi < bi)) { bv = ov; bi = oi; }
            }
            if (lane == 0) {
                int a = bi;
                sh_act[b] = a;
                sh_mask[b][a] = 1.0f;
                oA[(size_t)gb * Tt + t] = (float)a;
                float cx = pnt[((size_t)gb * Nn + a) * 2 + 0];
                float cy = pnt[((size_t)gb * Nn + a) * 2 + 1];
                oC[((size_t)gb * Tt + t) * 2 + 0] = cx;
                oC[((size_t)gb * Tt + t) * 2 + 1] = cy;
                if (t == 0) { sh_fx[b] = cx; sh_fy[b] = cy; }
                else {
                    float dx = cx - sh_px[b], dy = cy - sh_py[b];
                    sh_R[b] += sqrtf(dx * dx + dy * dy + 1e-10f);
                }
                sh_px[b] = cx; sh_py[b] = cy;
            }
        }
        __syncthreads();
    } // t loop

    // ---- R closing edge
    if (tid < Gg) {
        int b = tid; int gb = b0 + b;
        float dx = sh_fx[b] - sh_px[b], dy = sh_fy[b] - sh_py[b];
        oR[gb] = sh_R[b] + sqrtf(dx * dx + dy * dy + 1e-10f);
    }
    // ---- dec_last = context[b, last action]  (reuse sh_h)
    {
        int b = q4, h = jj;
        sh_h[b][h] = g_ctx[((size_t)(b0 + b) * Nn + sh_act[b]) * 128 + h];
    }
    __syncthreads();
    // ---- critic shortcut: hy = dec_last @ Wref_c (softmax over length-1 enc == 1)
    {
        int b = q4;
        float ha = 0.f;
        #pragma unroll 4
        for (int k = 0; k < 128; k++)
            ha = fmaf(Wrc[k * 128 + jj], sh_h[b][k], ha);
        sh_q[b][jj] = ha;
    }
    __syncthreads();
    {
        int b = q4;
        float za = 0.f;
        #pragma unroll 4
        for (int k = 0; k < 128; k++)
            za = fmaf(W1[k * 128 + jj], sh_q[b][k], za);
        sh_q2[b][jj] = fmaxf(za + b1[jj], 0.f);
    }
    __syncthreads();
    if (wid < Gg) {
        int b = wid; int gb = b0 + b;
        float s = 0.f;
        #pragma unroll
        for (int c4 = 0; c4 < 4; c4++) {
            int h = lane + 32 * c4;
            s = fmaf(sh_q2[b][h], W2[h], s);
        }
        #pragma unroll
        for (int o = 16; o; o >>= 1) s += __shfl_xor_sync(FULLMASK, s, o);
        if (lane == 0) oV[gb] = s + b2[0];
    }
}

extern "C" void kernel_launch(void* const* d_in, const int* in_sizes, int n_in,
                              void* d_out, int out_size) {
    const float* pnt  = (const float*)d_in[0];
    const float* Wemb = (const float*)d_in[1];
    const float* bemb = (const float*)d_in[2];
    const float* dini = (const float*)d_in[3];
    const float* Wi   = (const float*)d_in[4];
    const float* Wh   = (const float*)d_in[5];
    const float* bl   = (const float*)d_in[6];
    const float* Wqg  = (const float*)d_in[7];
    const float* Wrg  = (const float*)d_in[8];
    const float* vg   = (const float*)d_in[9];
    const float* Wqp  = (const float*)d_in[10];
    const float* Wrp  = (const float*)d_in[11];
    const float* vp   = (const float*)d_in[12];
    // d_in[13..16]: Wi_c, Wh_c, b_c, Wq_c — dead (softmax over length-1 enc)
    const float* Wrc  = (const float*)d_in[17];
    // d_in[18]: v_c — dead
    const float* W1   = (const float*)d_in[19];
    const float* b1   = (const float*)d_in[20];
    const float* W2   = (const float*)d_in[21];
    const float* b2   = (const float*)d_in[22];

    k_pre<<<(Bq * Nn) / 64 + 1, 512>>>(pnt, Wemb, bemb, Wrg, Wrp, Wi, dini);
    k_main<<<Bq / Gg, 512>>>(pnt, Wh, bl, Wqg, vg, Wqp, vp,
                             Wrc, W1, b1, W2, b2, (float*)d_out);
}

// round 5
// speedup vs baseline: 2.0513x; 1.1655x over previous
#include <cuda_runtime.h>
#include <math.h>
#include <stdint.h>

#define Bq 1024
#define Nn 50
#define Hh 128
#define Tt 50
#define Gg 2
#define FULLMASK 0xffffffffu

// Scratch (allocation-free rule: __device__ globals)
__device__ float g_ctx[Bq * Nn * Hh];
__device__ float g_eg [Bq * Nn * Hh];
__device__ float g_ep [Bq * Nn * Hh];
__device__ float g_xw [(size_t)Bq * Nn * 512];  // context @ Wi
__device__ float g_xw0[512];                    // dec_init @ Wi

__device__ __forceinline__ float my_tanh(float x) {
    float e = __expf(2.0f * x);
    return 1.0f - __fdividef(2.0f, e + 1.0f);
}
__device__ __forceinline__ float my_sig(float x) {
    return __fdividef(1.0f, 1.0f + __expf(-x));
}

// ---------------- Phase A: context, e_g, e_p, ctx@Wi ----------------
__global__ __launch_bounds__(512) void k_pre(
    const float* __restrict__ pnt, const float* __restrict__ Wemb,
    const float* __restrict__ bemb, const float* __restrict__ Wrg,
    const float* __restrict__ Wrp, const float* __restrict__ Wi,
    const float* __restrict__ dini)
{
    if (blockIdx.x == (Bq * Nn) / 64) {
        int j = threadIdx.x;
        float s = 0.f;
        #pragma unroll 4
        for (int k = 0; k < 128; k++) s = fmaf(dini[k], Wi[k * 512 + j], s);
        g_xw0[j] = s;
        return;
    }
    __shared__ __align__(16) float sctx[64][128];
    int row0 = blockIdx.x * 64;
    int tid = threadIdx.x;
    for (int i = tid; i < 64 * 128; i += 512) {
        int r = i >> 7, h = i & 127;
        int row = row0 + r;
        float px = pnt[row * 2 + 0], py = pnt[row * 2 + 1];
        float v = fmaf(px, Wemb[h], fmaf(py, Wemb[128 + h], bemb[h]));
        sctx[r][h] = v;
        g_ctx[(size_t)row * 128 + h] = v;
    }
    __syncthreads();
    int jj = tid & 127;
    int quarter = tid >> 7;
    int rbase = quarter * 16;

#define PRE_PASS(Wptr, LD, COLOFF, OUTptr, LDO)                                   \
    {                                                                             \
        float acc[16];                                                            \
        _Pragma("unroll")                                                         \
        for (int r = 0; r < 16; r++) acc[r] = 0.f;                                \
        for (int k4 = 0; k4 < 32; k4++) {                                         \
            float w0 = Wptr[(4 * k4 + 0) * LD + COLOFF + jj];                     \
            float w1 = Wptr[(4 * k4 + 1) * LD + COLOFF + jj];                     \
            float w2 = Wptr[(4 * k4 + 2) * LD + COLOFF + jj];                     \
            float w3 = Wptr[(4 * k4 + 3) * LD + COLOFF + jj];                     \
            _Pragma("unroll")                                                     \
            for (int r = 0; r < 16; r++) {                                        \
                float4 c = reinterpret_cast<const float4*>(&sctx[rbase + r][0])[k4]; \
                acc[r] = fmaf(w0, c.x, fmaf(w1, c.y, fmaf(w2, c.z, fmaf(w3, c.w, acc[r])))); \
            }                                                                     \
        }                                                                         \
        _Pragma("unroll")                                                         \
        for (int r = 0; r < 16; r++)                                              \
            OUTptr[(size_t)(row0 + rbase + r) * LDO + COLOFF + jj] = acc[r];      \
    }

    PRE_PASS(Wrg, 128, 0, g_eg, 128);
    PRE_PASS(Wrp, 128, 0, g_ep, 128);
    PRE_PASS(Wi, 512, 0,   g_xw, 512);
    PRE_PASS(Wi, 512, 128, g_xw, 512);
    PRE_PASS(Wi, 512, 256, g_xw, 512);
    PRE_PASS(Wi, 512, 384, g_xw, 512);
#undef PRE_PASS
}

// ---------------- Phase B+C: full T-loop, 4 CTAs/SM ----------------
__global__ __launch_bounds__(256, 4) void k_main(
    const float* __restrict__ pnt, const float* __restrict__ Wh,
    const float* __restrict__ bl,
    const float* __restrict__ Wqg, const float* __restrict__ vg,
    const float* __restrict__ Wqp, const float* __restrict__ vp,
    const float* __restrict__ Wrc, const float* __restrict__ W1,
    const float* __restrict__ b1, const float* __restrict__ W2,
    const float* __restrict__ b2, float* __restrict__ out)
{
    int b0 = blockIdx.x * Gg;
    int tid = threadIdx.x;
    int lane = tid & 31, wid = tid >> 5;   // 8 warps
    int jj = tid & 127;
    int half = tid >> 7;                   // 0..1 : k-half (gates) / batch id (others)

    __shared__ __align__(16) float4 sh_part[2][Gg][128];        // 8 KB gates partials
    __shared__ __align__(16) float sh_h[Gg][128], sh_c[Gg][128];
    __shared__ __align__(16) float sh_q[Gg][128], sh_q2[Gg][128];
    __shared__ float sh_u[Gg][52], sh_mask[Gg][52];
    __shared__ __align__(16) float sh_vg[128], sh_vp[128];
    __shared__ int   sh_act[Gg];
    __shared__ float sh_px[Gg], sh_py[Gg], sh_fx[Gg], sh_fy[Gg], sh_R[Gg];

    {   // init (256 threads == Gg*128 exactly)
        sh_h[half][jj] = 0.f; sh_c[half][jj] = 0.f;
        if (tid < Gg * 52) sh_mask[tid / 52][tid % 52] = 0.f;
        if (tid < 128) { sh_vg[tid] = vg[tid]; sh_vp[tid] = vp[tid]; }
        if (tid < Gg) sh_R[tid] = 0.f;
    }
    __syncthreads();

    float* oR  = out;
    float* oV  = out + Bq;
    float* oLP = out + 2 * Bq;
    float* oA  = oLP + (size_t)Bq * Tt * Nn;
    float* oC  = oA  + (size_t)Bq * Tt;
    float* oP  = oC  + (size_t)Bq * Tt * 2;

    const float4* Wh4 = reinterpret_cast<const float4*>(Wh);

    for (int t = 0; t < Tt; t++) {
        // ---- P0: gates partials, 2-way k-split (both batches per thread)
        {
            float4 a0 = make_float4(0.f, 0.f, 0.f, 0.f);
            float4 a1 = make_float4(0.f, 0.f, 0.f, 0.f);
            int k0 = half * 64;
            #pragma unroll 4
            for (int k = k0; k < k0 + 64; k++) {
                float4 wh = Wh4[k * 128 + jj];
                float h0 = sh_h[0][k], h1 = sh_h[1][k];
                a0.x = fmaf(wh.x, h0, a0.x); a0.y = fmaf(wh.y, h0, a0.y);
                a0.z = fmaf(wh.z, h0, a0.z); a0.w = fmaf(wh.w, h0, a0.w);
                a1.x = fmaf(wh.x, h1, a1.x); a1.y = fmaf(wh.y, h1, a1.y);
                a1.z = fmaf(wh.z, h1, a1.z); a1.w = fmaf(wh.w, h1, a1.w);
            }
            sh_part[half][0][jj] = a0;
            sh_part[half][1][jj] = a1;
        }
        __syncthreads();
        // ---- P1: fused reduce + x@Wi row + LSTM pointwise (thread = (b=half, j=jj))
        {
            int b = half, j = jj;
            const float* p0 = reinterpret_cast<const float*>(&sh_part[0][b][0]);
            const float* p1 = reinterpret_cast<const float*>(&sh_part[1][b][0]);
            const float* xw = (t == 0) ? g_xw0
                : g_xw + ((size_t)(b0 + b) * Nn + sh_act[b]) * 512;
            float gi = xw[j]       + p0[j]       + p1[j]       + bl[j];
            float gf = xw[128 + j] + p0[128 + j] + p1[128 + j] + bl[128 + j];
            float gg = xw[256 + j] + p0[256 + j] + p1[256 + j] + bl[256 + j];
            float go = xw[384 + j] + p0[384 + j] + p1[384 + j] + bl[384 + j];
            float c2 = my_sig(gf) * sh_c[b][j] + my_sig(gi) * my_tanh(gg);
            sh_c[b][j] = c2;
            sh_h[b][j] = my_sig(go) * my_tanh(c2);
        }
        __syncthreads();
        // ---- P3: q = h2 @ Wq_g (thread = (b, jj), split accumulators)
        {
            int b = half;
            float qa = 0.f, qb = 0.f;
            #pragma unroll 4
            for (int k = 0; k < 128; k += 2) {
                qa = fmaf(Wqg[k * 128 + jj],       sh_h[b][k],     qa);
                qb = fmaf(Wqg[(k + 1) * 128 + jj], sh_h[b][k + 1], qb);
            }
            sh_q[b][jj] = qa + qb;
        }
        __syncthreads();
        // ---- P4: u[b,n] = sum_h tanh(e_g+q)*v_g - 1e9*mask (100 rows / 8 warps, float4)
        for (int r = wid; r < Gg * Nn; r += 8) {
            int b = r >= Nn; int n = r - (b ? Nn : 0);
            const float4* eg4 = reinterpret_cast<const float4*>(
                g_eg + ((size_t)(b0 + b) * Nn + n) * 128);
            float4 e = eg4[lane];
            float4 q = reinterpret_cast<const float4*>(sh_q[b])[lane];
            float4 v = reinterpret_cast<const float4*>(sh_vg)[lane];
            float s = my_tanh(e.x + q.x) * v.x;
            s = fmaf(my_tanh(e.y + q.y), v.y, s);
            s = fmaf(my_tanh(e.z + q.z), v.z, s);
            s = fmaf(my_tanh(e.w + q.w), v.w, s);
            #pragma unroll
            for (int o = 16; o; o >>= 1) s += __shfl_xor_sync(FULLMASK, s, o);
            if (lane == 0) sh_u[b][n] = s - 1e9f * sh_mask[b][n];
        }
        __syncthreads();
        // ---- P5: softmax(u) -> p (warp b handles batch b)
        if (wid < Gg) {
            int b = wid;
            float l0 = sh_u[b][lane];
            float l1 = (lane < 18) ? sh_u[b][lane + 32] : -1e38f;
            float m = fmaxf(l0, l1);
            #pragma unroll
            for (int o = 16; o; o >>= 1) m = fmaxf(m, __shfl_xor_sync(FULLMASK, m, o));
            float e0 = __expf(l0 - m);
            float e1 = (lane < 18) ? __expf(l1 - m) : 0.f;
            float s = e0 + e1;
            #pragma unroll
            for (int o = 16; o; o >>= 1) s += __shfl_xor_sync(FULLMASK, s, o);
            float inv = __fdividef(1.f, s);
            sh_u[b][lane] = e0 * inv;
            if (lane < 18) sh_u[b][lane + 32] = e1 * inv;
        }
        __syncthreads();
        // ---- P6: glimpse g = p @ e_g -> sh_q
        {
            int b = half;
            const float* ep = g_eg + ((size_t)(b0 + b) * Nn) * 128 + jj;
            float ga = 0.f, gb2 = 0.f;
            #pragma unroll 2
            for (int n = 0; n < Nn; n += 2) {
                ga  = fmaf(sh_u[b][n],     ep[n * 128],       ga);
                gb2 = fmaf(sh_u[b][n + 1], ep[(n + 1) * 128], gb2);
            }
            sh_q[b][jj] = ga + gb2;
        }
        __syncthreads();
        // ---- P7: q2 = g @ Wq_p
        {
            int b = half;
            float qa = 0.f, qb = 0.f;
            #pragma unroll 4
            for (int k = 0; k < 128; k += 2) {
                qa = fmaf(Wqp[k * 128 + jj],       sh_q[b][k],     qa);
                qb = fmaf(Wqp[(k + 1) * 128 + jj], sh_q[b][k + 1], qb);
            }
            sh_q2[b][jj] = qa + qb;
        }
        __syncthreads();
        // ---- P8: logit = 10*tanh(u2) - 1e9*mask (float4)
        for (int r = wid; r < Gg * Nn; r += 8) {
            int b = r >= Nn; int n = r - (b ? Nn : 0);
            const float4* ep4 = reinterpret_cast<const float4*>(
                g_ep + ((size_t)(b0 + b) * Nn + n) * 128);
            float4 e = ep4[lane];
            float4 q = reinterpret_cast<const float4*>(sh_q2[b])[lane];
            float4 v = reinterpret_cast<const float4*>(sh_vp)[lane];
            float s = my_tanh(e.x + q.x) * v.x;
            s = fmaf(my_tanh(e.y + q.y), v.y, s);
            s = fmaf(my_tanh(e.z + q.z), v.z, s);
            s = fmaf(my_tanh(e.w + q.w), v.w, s);
            #pragma unroll
            for (int o = 16; o; o >>= 1) s += __shfl_xor_sync(FULLMASK, s, o);
            if (lane == 0) sh_u[b][n] = 10.0f * my_tanh(s) - 1e9f * sh_mask[b][n];
        }
        __syncthreads();
        // ---- P9: log_softmax / softmax / argmax / outputs / state
        if (wid < Gg) {
            int b = wid; int gb = b0 + b;
            float l0 = sh_u[b][lane];
            float l1 = (lane < 18) ? sh_u[b][lane + 32] : -1e38f;
            float m = fmaxf(l0, l1);
            #pragma unroll
            for (int o = 16; o; o >>= 1) m = fmaxf(m, __shfl_xor_sync(FULLMASK, m, o));
            float e0 = __expf(l0 - m);
            float e1 = (lane < 18) ? __expf(l1 - m) : 0.f;
            float s = e0 + e1;
            #pragma unroll
            for (int o = 16; o; o >>= 1) s += __shfl_xor_sync(FULLMASK, s, o);
            float lgs = logf(s);
            float p0 = e0 / s;
            float p1 = e1 / s;
            size_t base = ((size_t)gb * Tt + t) * Nn;
            oLP[base + lane] = (l0 - m) - lgs;
            oP [base + lane] = p0;
            if (lane < 18) {
                oLP[base + lane + 32] = (l1 - m) - lgs;
                oP [base + lane + 32] = p1;
            }
            float bv = p0; int bi = lane;
            if (lane < 18 && p1 > bv) { bv = p1; bi = lane + 32; }
            #pragma unroll
            for (int o = 16; o; o >>= 1) {
                float ov = __shfl_down_sync(FULLMASK, bv, o);
                int   oi = __shfl_down_sync(FULLMASK, bi, o);
                if (ov > bv || (ov == bv && oi < bi)) { bv = ov; bi = oi; }
            }
            if (lane == 0) {
                int a = bi;
                sh_act[b] = a;
                sh_mask[b][a] = 1.0f;
                oA[(size_t)gb * Tt + t] = (float)a;
                float cx = pnt[((size_t)gb * Nn + a) * 2 + 0];
                float cy = pnt[((size_t)gb * Nn + a) * 2 + 1];
                oC[((size_t)gb * Tt + t) * 2 + 0] = cx;
                oC[((size_t)gb * Tt + t) * 2 + 1] = cy;
                if (t == 0) { sh_fx[b] = cx; sh_fy[b] = cy; }
                else {
                    float dx = cx - sh_px[b], dy = cy - sh_py[b];
                    sh_R[b] += sqrtf(dx * dx + dy * dy + 1e-10f);
                }
                sh_px[b] = cx; sh_py[b] = cy;
            }
        }
        __syncthreads();
    } // t loop

    // ---- R closing edge
    if (tid < Gg) {
        int b = tid; int gb = b0 + b;
        float dx = sh_fx[b] - sh_px[b], dy = sh_fy[b] - sh_py[b];
        oR[gb] = sh_R[b] + sqrtf(dx * dx + dy * dy + 1e-10f);
    }
    // ---- dec_last = context[b, last action]  (reuse sh_h)
    sh_h[half][jj] = g_ctx[((size_t)(b0 + half) * Nn + sh_act[half]) * 128 + jj];
    __syncthreads();
    // ---- critic shortcut: hy = dec_last @ Wref_c (softmax over length-1 enc == 1)
    {
        int b = half;
        float ha = 0.f, hb = 0.f;
        #pragma unroll 4
        for (int k = 0; k < 128; k += 2) {
            ha = fmaf(Wrc[k * 128 + jj],       sh_h[b][k],     ha);
            hb = fmaf(Wrc[(k + 1) * 128 + jj], sh_h[b][k + 1], hb);
        }
        sh_q[b][jj] = ha + hb;
    }
    __syncthreads();
    {
        int b = half;
        float za = 0.f, zb = 0.f;
        #pragma unroll 4
        for (int k = 0; k < 128; k += 2) {
            za = fmaf(W1[k * 128 + jj],       sh_q[b][k],     za);
            zb = fmaf(W1[(k + 1) * 128 + jj], sh_q[b][k + 1], zb);
        }
        sh_q2[b][jj] = fmaxf(za + zb + b1[jj], 0.f);
    }
    __syncthreads();
    if (wid < Gg) {
        int b = wid; int gb = b0 + b;
        float4 zq = reinterpret_cast<const float4*>(sh_q2[b])[lane];
        float4 w2 = reinterpret_cast<const float4*>(W2)[lane];
        float s = zq.x * w2.x + zq.y * w2.y + zq.z * w2.z + zq.w * w2.w;
        #pragma unroll
        for (int o = 16; o; o >>= 1) s += __shfl_xor_sync(FULLMASK, s, o);
        if (lane == 0) oV[gb] = s + b2[0];
    }
}

extern "C" void kernel_launch(void* const* d_in, const int* in_sizes, int n_in,
                              void* d_out, int out_size) {
    const float* pnt  = (const float*)d_in[0];
    const float* Wemb = (const float*)d_in[1];
    const float* bemb = (const float*)d_in[2];
    const float* dini = (const float*)d_in[3];
    const float* Wi   = (const float*)d_in[4];
    const float* Wh   = (const float*)d_in[5];
    const float* bl   = (const float*)d_in[6];
    const float* Wqg  = (const float*)d_in[7];
    const float* Wrg  = (const float*)d_in[8];
    const float* vg   = (const float*)d_in[9];
    const float* Wqp  = (const float*)d_in[10];
    const float* Wrp  = (const float*)d_in[11];
    const float* vp   = (const float*)d_in[12];
    // d_in[13..16]: Wi_c, Wh_c, b_c, Wq_c — dead (softmax over length-1 enc)
    const float* Wrc  = (const float*)d_in[17];
    // d_in[18]: v_c — dead
    const float* W1   = (const float*)d_in[19];
    const float* b1   = (const float*)d_in[20];
    const float* W2   = (const float*)d_in[21];
    const float* b2   = (const float*)d_in[22];

    k_pre<<<(Bq * Nn) / 64 + 1, 512>>>(pnt, Wemb, bemb, Wrg, Wrp, Wi, dini);
    k_main<<<Bq / Gg, 256>>>(pnt, Wh, bl, Wqg, vg, Wqp, vp,
                             Wrc, W1, b1, W2, b2, (float*)d_out);
}